// round 14
// baseline (speedup 1.0000x reference)
#include <cuda_runtime.h>
#include <cuda_fp16.h>
#include <math.h>

#define NN 5000
#define TT 100
#define INDIM 32
#define FEAT 64
#define HIDD 64
#define OUTD 8
#define NHEADS 4
#define EE 160000
#define FIN 72
#define SSTR 88   // smem half stride (44 uints) for k_pre tiles

// ---------------- scratch (device globals; POD types only) -----------------
__device__ unsigned int g_embh[(size_t)TT * NN * 32];         // fp16 emb [T][N][64]
__device__ unsigned int g_xw[(size_t)TT * NN * 128];          // fp16 x@Wih+b
__device__ unsigned int g_wh[13 * 64 * 44];                   // fp16 W chunks [c][n][k/2]
__device__ unsigned int g_w2h[13 * 64 * 8];                   // fp16 W rows 64-71 [c][n][8u]
__device__ float        g_bias[13 * 64];
__device__ unsigned int g_pre[(size_t)TT * NN * 416];         // fp16 emb@W+b, all t
__device__ float        g_q[(size_t)NN * 256];                // fp32 q
__device__ float        g_skip[(size_t)NN * 64];              // fp32 skip
__device__ unsigned int g_kh[(size_t)NN * 128];               // fp16 k
__device__ unsigned int g_vh[(size_t)NN * 128];               // fp16 v
__device__ float        g_theta[(size_t)(TT + 1) * NN * OUTD];// fp32 theta history
__device__ unsigned int g_thetah[(size_t)NN * 4];             // fp16 theta (rolling)
__device__ int          g_cnt[NN];
__device__ int          g_rowptr[NN + 1];
__device__ int          g_cursor[NN];
__device__ int          g_csrsrc[EE];

__device__ __forceinline__ float fsig(float x) {
    return __fdividef(1.f, 1.f + __expf(-x));
}
__device__ __forceinline__ float ftanh(float x) {
    return 2.f * fsig(2.f * x) - 1.f;
}

__device__ __forceinline__ void mma16816(float* c, const unsigned* a, const unsigned* b) {
    asm volatile(
        "mma.sync.aligned.m16n8k16.row.col.f32.f16.f16.f32 "
        "{%0,%1,%2,%3}, {%4,%5,%6,%7}, {%8,%9}, {%0,%1,%2,%3};"
        : "+f"(c[0]), "+f"(c[1]), "+f"(c[2]), "+f"(c[3])
        : "r"(a[0]), "r"(a[1]), "r"(a[2]), "r"(a[3]), "r"(b[0]), "r"(b[1]));
}

// ---------------- fused init + weight prep ---------------------------------
__global__ void k_initwprep(const float* __restrict__ Wq, const float* __restrict__ bq,
                            const float* __restrict__ Wk, const float* __restrict__ bk,
                            const float* __restrict__ Wv, const float* __restrict__ bv,
                            const float* __restrict__ Wsk, const float* __restrict__ bsk) {
    int tid = threadIdx.x;
    if (blockIdx.x < 13) {
        int chunk = blockIdx.x;
        const float* Wsrc; const float* bsrc; int cofs, width;
        if (chunk < 4)       { Wsrc = Wq;  bsrc = bq;  cofs = chunk * 64;       width = 256; }
        else if (chunk < 8)  { Wsrc = Wk;  bsrc = bk;  cofs = (chunk - 4) * 64; width = 256; }
        else if (chunk < 12) { Wsrc = Wv;  bsrc = bv;  cofs = (chunk - 8) * 64; width = 256; }
        else                 { Wsrc = Wsk; bsrc = bsk; cofs = 0;                width = 64;  }
        for (int i = tid; i < 64 * 44; i += 256) {
            int n = i / 44, ku = i - n * 44;
            unsigned val = 0u;
            if (ku < 40) {
                int k0 = ku * 2, k1 = k0 + 1;
                float f0 = (k0 < 72) ? Wsrc[k0 * width + cofs + n] : 0.f;
                float f1 = (k1 < 72) ? Wsrc[k1 * width + cofs + n] : 0.f;
                union { unsigned u; __half2 h; } p; p.h = __floats2half2_rn(f0, f1);
                val = p.u;
            }
            g_wh[(chunk * 64 + n) * 44 + ku] = val;
        }
        // W rows 64-71 (theta part), fp16, padded to 8 uints per n
        for (int i = tid; i < 64 * 8; i += 256) {
            int n = i >> 3, j = i & 7;
            unsigned val = 0u;
            if (j < 4) {
                int d0 = j * 2, d1 = d0 + 1;
                float f0 = Wsrc[(64 + d0) * width + cofs + n];
                float f1 = Wsrc[(64 + d1) * width + cofs + n];
                union { unsigned u; __half2 h; } p; p.h = __floats2half2_rn(f0, f1);
                val = p.u;
            }
            g_w2h[(chunk * 64 + n) * 8 + j] = val;
        }
        if (tid < 64) g_bias[chunk * 64 + tid] = bsrc[cofs + tid];
    } else {
        int i = (blockIdx.x - 13) * 256 + tid;
        if (i < NN) g_cnt[i] = 0;
        if (i < NN * OUTD) g_theta[i] = 0.f;
        if (i < NN * 4) g_thetah[i] = 0u;
    }
}

// ---------------- CSR build ------------------------------------------------
__global__ void k_count(const int* __restrict__ ei) {
    int e = blockIdx.x * 256 + threadIdx.x;
    if (e < EE) atomicAdd(&g_cnt[ei[EE + e]], 1);
}

__global__ void k_scan() {
    __shared__ int ss[256];
    int tid = threadIdx.x;
    int i0 = tid * 20;
    int sum = 0;
    for (int i = i0; i < i0 + 20 && i < NN; i++) sum += g_cnt[i];
    ss[tid] = sum;
    __syncthreads();
    if (tid == 0) {
        int run = 0;
        for (int i = 0; i < 256; i++) { int v = ss[i]; ss[i] = run; run += v; }
    }
    __syncthreads();
    int run = ss[tid];
    for (int i = i0; i < i0 + 20 && i < NN; i++) {
        g_rowptr[i] = run;
        g_cursor[i] = run;
        run += g_cnt[i];
    }
    if (tid == 255) g_rowptr[NN] = run;
}

__global__ void k_scatter(const int* __restrict__ ei) {
    int e = blockIdx.x * 256 + threadIdx.x;
    if (e < EE) {
        int d = ei[EE + e];
        int pos = atomicAdd(&g_cursor[d], 1);
        g_csrsrc[pos] = ei[e];
    }
}

// ---------------- k_xw: XW = x @ Wih + bias (all t, HMMA) ------------------
__global__ void k_xw(const float* __restrict__ x, const float* __restrict__ Wih,
                     const float* __restrict__ bih, const float* __restrict__ bhh) {
    __shared__ __align__(16) __half sA[64 * 40];
    __shared__ __align__(16) __half sB[256 * 40];
    __shared__ float sBias[256];
    int tid = threadIdx.x;
    int nb0 = blockIdx.x * 64;
    int t = blockIdx.y;

    for (int i = tid; i < 64 * 32; i += 256) {
        int r = i >> 5, k = i & 31;
        int node = nb0 + r;
        float v = (node < NN) ? x[((size_t)node * TT + t) * 32 + k] : 0.f;
        sA[r * 40 + k] = __float2half(v);
    }
    for (int i = tid; i < 32 * 256; i += 256) {
        int n = i & 255, k = i >> 8;
        sB[n * 40 + k] = __float2half(Wih[k * 256 + n]);
    }
    sBias[tid] = bih[tid] + bhh[tid];
    __syncthreads();

    int wid = tid >> 5, l = tid & 31;
    int wr = wid >> 2, wc = wid & 3;
    int g = l >> 2, tg = l & 3;

    float acc[2][8][4] = {};
#pragma unroll
    for (int ks = 0; ks < 2; ks++) {
        int kb = ks * 16;
        unsigned a[2][4], b[8][2];
#pragma unroll
        for (int ms = 0; ms < 2; ms++) {
            int row = wr * 32 + ms * 16 + g;
            const __half* p0 = sA + row * 40 + kb + tg * 2;
            const __half* p1 = sA + (row + 8) * 40 + kb + tg * 2;
            a[ms][0] = *(const unsigned*)p0;
            a[ms][1] = *(const unsigned*)p1;
            a[ms][2] = *(const unsigned*)(p0 + 8);
            a[ms][3] = *(const unsigned*)(p1 + 8);
        }
#pragma unroll
        for (int ns = 0; ns < 8; ns++) {
            int n = wc * 64 + ns * 8 + g;
            const __half* p = sB + n * 40 + kb + tg * 2;
            b[ns][0] = *(const unsigned*)p;
            b[ns][1] = *(const unsigned*)(p + 8);
        }
#pragma unroll
        for (int ms = 0; ms < 2; ms++)
#pragma unroll
            for (int ns = 0; ns < 8; ns++)
                mma16816(acc[ms][ns], a[ms], b[ns]);
    }

#pragma unroll
    for (int ms = 0; ms < 2; ms++) {
        int row0 = nb0 + wr * 32 + ms * 16 + g;
#pragma unroll
        for (int ns = 0; ns < 8; ns++) {
            int col = wc * 64 + ns * 8 + tg * 2;
            float b0 = sBias[col], b1 = sBias[col + 1];
            union { unsigned u; __half2 h; } p0, p1;
            p0.h = __floats2half2_rn(acc[ms][ns][0] + b0, acc[ms][ns][1] + b1);
            p1.h = __floats2half2_rn(acc[ms][ns][2] + b0, acc[ms][ns][3] + b1);
            int cu = col >> 1;
            if (row0 < NN)     g_xw[((size_t)t * NN + row0) * 128 + cu] = p0.u;
            if (row0 + 8 < NN) g_xw[((size_t)t * NN + row0 + 8) * 128 + cu] = p1.u;
        }
    }
}

// ---------------- k_lstm2: HMMA recurrence, 32 nodes/block -----------------
__global__ void k_lstm2(const float* __restrict__ Whh) {
    __shared__ __align__(16) __half sBt[256 * 72];   // Whh^T [n][k]
    __shared__ __align__(16) __half sH[2 * 32 * 72]; // double-buffered h

    int tid = threadIdx.x;
    int nb0 = blockIdx.x * 32;

    for (int i = tid; i < 64 * 256; i += 256) {
        int n = i & 255, k = i >> 8;
        sBt[n * 72 + k] = __float2half(Whh[k * 256 + n]);
    }
    for (int i = tid; i < 32 * 72; i += 256) sH[i] = __float2half(0.f);

    int wid = tid >> 5, l = tid & 31;
    int wr = wid >> 2, wc = wid & 3;
    int g = l >> 2, tg = l & 3;

    int row0 = wr * 16 + g;
    int node0 = nb0 + row0, node1 = node0 + 8;
    bool v0 = node0 < NN, v1 = node1 < NN;

    float cst[8];
#pragma unroll
    for (int i = 0; i < 8; i++) cst[i] = 0.f;

    unsigned cur[16];
#pragma unroll
    for (int j = 0; j < 8; j++) {
        int colu = (wc + 4 * j) * 4 + tg;
        cur[j * 2]     = v0 ? g_xw[(size_t)node0 * 128 + colu] : 0u;
        cur[j * 2 + 1] = v1 ? g_xw[(size_t)node1 * 128 + colu] : 0u;
    }
    __syncthreads();

    for (int t = 0; t < TT; t++) {
        const __half* sHr = sH + (t & 1) * 32 * 72;
        __half* sHw = sH + ((t + 1) & 1) * 32 * 72;

        float acc[8][4];
#pragma unroll
        for (int j = 0; j < 8; j++) {
            union { unsigned u; __half2 h; } p0, p1;
            p0.u = cur[j * 2]; p1.u = cur[j * 2 + 1];
            float2 f0 = __half22float2(p0.h), f1 = __half22float2(p1.h);
            acc[j][0] = f0.x; acc[j][1] = f0.y;
            acc[j][2] = f1.x; acc[j][3] = f1.y;
        }
        if (t + 1 < TT) {
            size_t base = (size_t)(t + 1) * NN;
#pragma unroll
            for (int j = 0; j < 8; j++) {
                int colu = (wc + 4 * j) * 4 + tg;
                cur[j * 2]     = v0 ? g_xw[(base + node0) * 128 + colu] : 0u;
                cur[j * 2 + 1] = v1 ? g_xw[(base + node1) * 128 + colu] : 0u;
            }
        }

#pragma unroll
        for (int ks = 0; ks < 4; ks++) {
            int kb = ks * 16;
            unsigned a[4], b[8][2];
            const __half* p0 = sHr + row0 * 72 + kb + tg * 2;
            const __half* p1 = sHr + (row0 + 8) * 72 + kb + tg * 2;
            a[0] = *(const unsigned*)p0;
            a[1] = *(const unsigned*)p1;
            a[2] = *(const unsigned*)(p0 + 8);
            a[3] = *(const unsigned*)(p1 + 8);
#pragma unroll
            for (int j = 0; j < 8; j++) {
                int n = (wc + 4 * j) * 8 + g;
                const __half* p = sBt + n * 72 + kb + tg * 2;
                b[j][0] = *(const unsigned*)p;
                b[j][1] = *(const unsigned*)(p + 8);
            }
#pragma unroll
            for (int j = 0; j < 8; j++)
                mma16816(acc[j], a, b[j]);
        }

#pragma unroll
        for (int p = 0; p < 2; p++)
#pragma unroll
            for (int rh = 0; rh < 2; rh++) {
                int row = row0 + rh * 8;
                int node = nb0 + row;
                float hv[2];
#pragma unroll
                for (int ch = 0; ch < 2; ch++) {
                    int ri = rh * 2 + ch;
                    float iv = fsig(acc[p][ri]);
                    float fv = fsig(acc[2 + p][ri]);
                    float gv = ftanh(acc[4 + p][ri]);
                    float ov = fsig(acc[6 + p][ri]);
                    int ci = p * 4 + rh * 2 + ch;
                    cst[ci] = fv * cst[ci] + iv * gv;
                    hv[ch] = ov * ftanh(cst[ci]);
                }
                int d = wc * 8 + p * 32 + tg * 2;
                __half2 h2 = __floats2half2_rn(hv[0], hv[1]);
                *(__half2*)(sHw + row * 72 + d) = h2;
                if (node < NN) {
                    union { __half2 h; unsigned u; } cv; cv.h = h2;
                    g_embh[((size_t)t * NN + node) * 32 + (d >> 1)] = cv.u;
                }
            }
        __syncthreads();
    }
}

// ---------------- k_pre: PRE = emb @ W[0:64] + bias, ALL t -----------------
// one flat GEMM [T*N x 64] @ [64 x 832]; grid (13, 3907), 128-row tiles.
__global__ void k_pre() {
    __shared__ __align__(16) __half sA[128 * SSTR];
    __shared__ __align__(16) __half sBt[64 * SSTR];
    __shared__ float sBias[64];

    int chunk = blockIdx.x;
    int tid = threadIdx.x;
    size_t rb0 = (size_t)blockIdx.y * 128;
    const size_t NR = (size_t)TT * NN;
    unsigned* sAu = (unsigned*)sA;
    unsigned* sBu = (unsigned*)sBt;

    for (int i = tid; i < 128 * 8; i += 256) {
        int r = i >> 3, j = i & 7;
        size_t row = rb0 + r;
        uint4 v = make_uint4(0u, 0u, 0u, 0u);
        if (row < NR) v = *(const uint4*)(g_embh + row * 32 + j * 4);
        *(uint4*)(sAu + r * 44 + j * 4) = v;
    }
    for (int i = tid; i < 64 * 8; i += 256) {
        int n = i >> 3, j = i & 7;
        *(uint4*)(sBu + n * 44 + j * 4) =
            *(const uint4*)(g_wh + (size_t)(chunk * 64 + n) * 44 + j * 4);
    }
    if (tid < 64) sBias[tid] = g_bias[chunk * 64 + tid];
    __syncthreads();

    int wid = tid >> 5, l = tid & 31;
    int wr = wid >> 1, wc = wid & 1;
    int g = l >> 2, tg = l & 3;

    float c[2][4][4] = {};
#pragma unroll
    for (int ks = 0; ks < 4; ks++) {       // K = 64 only (emb part)
        int kb = ks * 16;
        unsigned a[2][4], b[4][2];
#pragma unroll
        for (int ms = 0; ms < 2; ms++) {
            int row = wr * 32 + ms * 16 + g;
            const __half* p0 = sA + row * SSTR + kb + tg * 2;
            const __half* p1 = sA + (row + 8) * SSTR + kb + tg * 2;
            a[ms][0] = *(const unsigned*)p0;
            a[ms][1] = *(const unsigned*)p1;
            a[ms][2] = *(const unsigned*)(p0 + 8);
            a[ms][3] = *(const unsigned*)(p1 + 8);
        }
#pragma unroll
        for (int ns = 0; ns < 4; ns++) {
            int n = wc * 32 + ns * 8 + g;
            const __half* p = sBt + n * SSTR + kb + tg * 2;
            b[ns][0] = *(const unsigned*)p;
            b[ns][1] = *(const unsigned*)(p + 8);
        }
#pragma unroll
        for (int ms = 0; ms < 2; ms++)
#pragma unroll
            for (int ns = 0; ns < 4; ns++)
                mma16816(c[ms][ns], a[ms], b[ns]);
    }

#pragma unroll
    for (int ms = 0; ms < 2; ms++) {
        size_t row0 = rb0 + wr * 32 + ms * 16 + g;
#pragma unroll
        for (int ns = 0; ns < 4; ns++) {
            int col = wc * 32 + ns * 8 + tg * 2;
            float b0 = sBias[col], b1 = sBias[col + 1];
            union { unsigned u; __half2 h; } p0, p1;
            p0.h = __floats2half2_rn(c[ms][ns][0] + b0, c[ms][ns][1] + b1);
            p1.h = __floats2half2_rn(c[ms][ns][2] + b0, c[ms][ns][3] + b1);
            int cu = chunk * 32 + (col >> 1);
            if (row0 < NR)     g_pre[row0 * 416 + cu] = p0.u;
            if (row0 + 8 < NR) g_pre[(row0 + 8) * 416 + cu] = p1.u;
        }
    }
}

// ---------------- per-step: OUT = PRE[t] + theta @ W[64:72] ----------------
// tiny K=8 HMMA (1 k-step) + PRE add in epilogue. grid (13, 40).
__global__ void k_qkv2(int t) {
    __shared__ __align__(16) __half sA[128 * 24];   // theta, stride 24 halves
    __shared__ __align__(16) __half sBt[64 * 24];   // W2 chunk

    int chunk = blockIdx.x;
    int tid = threadIdx.x;
    int nb0 = blockIdx.y * 128;
    unsigned* sAu = (unsigned*)sA;
    unsigned* sBu = (unsigned*)sBt;

    for (int i = tid; i < 128 * 2; i += 256) {
        int r = i >> 1, j = i & 1;              // j=0: theta, j=1: zero pad
        int node = nb0 + r;
        uint4 v = make_uint4(0u, 0u, 0u, 0u);
        if (j == 0 && node < NN) v = *(const uint4*)(g_thetah + (size_t)node * 4);
        *(uint4*)(sAu + r * 12 + j * 4) = v;
    }
    for (int i = tid; i < 64 * 2; i += 256) {
        int n = i >> 1, j = i & 1;
        uint4 v = make_uint4(0u, 0u, 0u, 0u);
        if (j == 0) v = *(const uint4*)(g_w2h + (size_t)(chunk * 64 + n) * 8);
        *(uint4*)(sBu + n * 12 + j * 4) = v;
    }
    __syncthreads();

    int wid = tid >> 5, l = tid & 31;
    int wr = wid >> 1, wc = wid & 1;
    int g = l >> 2, tg = l & 3;

    float c[2][4][4] = {};
    {
        unsigned a[2][4], b[4][2];
#pragma unroll
        for (int ms = 0; ms < 2; ms++) {
            int row = wr * 32 + ms * 16 + g;
            const __half* p0 = sA + row * 24 + tg * 2;
            const __half* p1 = sA + (row + 8) * 24 + tg * 2;
            a[ms][0] = *(const unsigned*)p0;
            a[ms][1] = *(const unsigned*)p1;
            a[ms][2] = *(const unsigned*)(p0 + 8);
            a[ms][3] = *(const unsigned*)(p1 + 8);
        }
#pragma unroll
        for (int ns = 0; ns < 4; ns++) {
            int n = wc * 32 + ns * 8 + g;
            const __half* p = sBt + n * 24 + tg * 2;
            b[ns][0] = *(const unsigned*)p;
            b[ns][1] = *(const unsigned*)(p + 8);
        }
#pragma unroll
        for (int ms = 0; ms < 2; ms++)
#pragma unroll
            for (int ns = 0; ns < 4; ns++)
                mma16816(c[ms][ns], a[ms], b[ns]);
    }

#pragma unroll
    for (int ms = 0; ms < 2; ms++) {
        int row0 = nb0 + wr * 32 + ms * 16 + g;
#pragma unroll
        for (int ns = 0; ns < 4; ns++) {
            int col = wc * 32 + ns * 8 + tg * 2;
            int cu = chunk * 32 + (col >> 1);
            float o0 = c[ms][ns][0], o1 = c[ms][ns][1];
            float o2 = c[ms][ns][2], o3 = c[ms][ns][3];
            // add PRE
            if (row0 < NN) {
                union { unsigned u; __half2 h; } pu;
                pu.u = g_pre[((size_t)t * NN + row0) * 416 + cu];
                float2 f = __half22float2(pu.h);
                o0 += f.x; o1 += f.y;
            }
            if (row0 + 8 < NN) {
                union { unsigned u; __half2 h; } pu;
                pu.u = g_pre[((size_t)t * NN + row0 + 8) * 416 + cu];
                float2 f = __half22float2(pu.h);
                o2 += f.x; o3 += f.y;
            }
            if (chunk < 4) {
                if (row0 < NN)
                    *(float2*)(g_q + (size_t)row0 * 256 + chunk * 64 + col) = make_float2(o0, o1);
                if (row0 + 8 < NN)
                    *(float2*)(g_q + (size_t)(row0 + 8) * 256 + chunk * 64 + col) = make_float2(o2, o3);
            } else if (chunk < 12) {
                unsigned int* base = (chunk < 8) ? g_kh : g_vh;
                int cofs2 = ((chunk < 8) ? (chunk - 4) : (chunk - 8)) * 32 + (col >> 1);
                union { unsigned u; __half2 h; } p0, p1;
                p0.h = __floats2half2_rn(o0, o1);
                p1.h = __floats2half2_rn(o2, o3);
                if (row0 < NN)     base[(size_t)row0 * 128 + cofs2] = p0.u;
                if (row0 + 8 < NN) base[(size_t)(row0 + 8) * 128 + cofs2] = p1.u;
            } else {
                if (row0 < NN)
                    *(float2*)(g_skip + (size_t)row0 * 64 + col) = make_float2(o0, o1);
                if (row0 + 8 < NN)
                    *(float2*)(g_skip + (size_t)(row0 + 8) * 64 + col) = make_float2(o2, o3);
            }
        }
    }
}

// ---------------- per-step edge attention + epilogue -----------------------
__device__ __forceinline__ float dot8h(const float* q, uint4 r) {
    union { uint4 u; __half2 h[4]; } pk; pk.u = r;
    float2 f0 = __half22float2(pk.h[0]);
    float2 f1 = __half22float2(pk.h[1]);
    float2 f2 = __half22float2(pk.h[2]);
    float2 f3 = __half22float2(pk.h[3]);
    return q[0]*f0.x + q[1]*f0.y + q[2]*f1.x + q[3]*f1.y
         + q[4]*f2.x + q[5]*f2.y + q[6]*f3.x + q[7]*f3.y;
}
__device__ __forceinline__ void acc8h(float* acc, float p, uint4 r) {
    union { uint4 u; __half2 h[4]; } pk; pk.u = r;
    float2 f0 = __half22float2(pk.h[0]);
    float2 f1 = __half22float2(pk.h[1]);
    float2 f2 = __half22float2(pk.h[2]);
    float2 f3 = __half22float2(pk.h[3]);
    acc[0] += p * f0.x; acc[1] += p * f0.y;
    acc[2] += p * f1.x; acc[3] += p * f1.y;
    acc[4] += p * f2.x; acc[5] += p * f2.y;
    acc[6] += p * f3.x; acc[7] += p * f3.y;
}

__global__ void k_edge(int t, const float* __restrict__ Wmlp) {
    __shared__ float sWm[8 * 64];
    int tid = threadIdx.x;
    for (int i = tid; i < 512; i += 256) {
        int d = i >> 3, o = i & 7;
        sWm[o * 64 + d] = Wmlp[i];
    }
    __syncthreads();

    int wid = tid >> 5, l = tid & 31;
    int n = blockIdx.x * 8 + wid;

    float q[8];
    {
        const float* qp = g_q + (size_t)n * 256 + l * 8;
        float4 q0 = *(const float4*)qp, q1 = *(const float4*)(qp + 4);
        q[0]=q0.x; q[1]=q0.y; q[2]=q0.z; q[3]=q0.w;
        q[4]=q1.x; q[5]=q1.y; q[6]=q1.z; q[7]=q1.w;
    }
    int s = g_rowptr[n], e = g_rowptr[n + 1];
    float den = 0.f;
    float acc[8] = {};
    int koff = l * 4;

    // pipeline: k rows prefetched one batch ahead, indices two ahead
    int nfull = (e - s) >> 2;
    int ip = s;
    int ia0, ia1, ia2, ia3, ib0, ib1, ib2, ib3;
    uint4 kc0, kc1, kc2, kc3;
    if (nfull > 0) {
        ia0 = g_csrsrc[ip];     ia1 = g_csrsrc[ip + 1];
        ia2 = g_csrsrc[ip + 2]; ia3 = g_csrsrc[ip + 3]; ip += 4;
        kc0 = *(const uint4*)(g_kh + (size_t)ia0 * 128 + koff);
        kc1 = *(const uint4*)(g_kh + (size_t)ia1 * 128 + koff);
        kc2 = *(const uint4*)(g_kh + (size_t)ia2 * 128 + koff);
        kc3 = *(const uint4*)(g_kh + (size_t)ia3 * 128 + koff);
        if (nfull > 1) {
            ib0 = g_csrsrc[ip];     ib1 = g_csrsrc[ip + 1];
            ib2 = g_csrsrc[ip + 2]; ib3 = g_csrsrc[ip + 3]; ip += 4;
        }
    }
    for (int b = 0; b < nfull; b++) {
        // v of current batch (consumed late; latency hidden by dot/shfl/exp)
        uint4 v0 = *(const uint4*)(g_vh + (size_t)ia0 * 128 + koff);
        uint4 v1 = *(const uint4*)(g_vh + (size_t)ia1 * 128 + koff);
        uint4 v2 = *(const uint4*)(g_vh + (size_t)ia2 * 128 + koff);
        uint4 v3 = *(const uint4*)(g_vh + (size_t)ia3 * 128 + koff);
        bool more = b + 1 < nfull;
        uint4 kn0, kn1, kn2, kn3;
        if (more) {
            kn0 = *(const uint4*)(g_kh + (size_t)ib0 * 128 + koff);
            kn1 = *(const uint4*)(g_kh + (size_t)ib1 * 128 + koff);
            kn2 = *(const uint4*)(g_kh + (size_t)ib2 * 128 + koff);
            kn3 = *(const uint4*)(g_kh + (size_t)ib3 * 128 + koff);
        }
        bool more2 = b + 2 < nfull;
        int ic0, ic1, ic2, ic3;
        if (more2) {
            ic0 = g_csrsrc[ip];     ic1 = g_csrsrc[ip + 1];
            ic2 = g_csrsrc[ip + 2]; ic3 = g_csrsrc[ip + 3]; ip += 4;
        }
        float d0 = dot8h(q, kc0), d1 = dot8h(q, kc1);
        float d2 = dot8h(q, kc2), d3 = dot8h(q, kc3);
#pragma unroll
        for (int r = 1; r <= 4; r <<= 1) {
            d0 += __shfl_xor_sync(0xffffffffu, d0, r);
            d1 += __shfl_xor_sync(0xffffffffu, d1, r);
            d2 += __shfl_xor_sync(0xffffffffu, d2, r);
            d3 += __shfl_xor_sync(0xffffffffu, d3, r);
        }
        float p0 = __expf(d0 * 0.125f), p1 = __expf(d1 * 0.125f);
        float p2 = __expf(d2 * 0.125f), p3 = __expf(d3 * 0.125f);
        den += (p0 + p1) + (p2 + p3);
        acc8h(acc, p0, v0); acc8h(acc, p1, v1);
        acc8h(acc, p2, v2); acc8h(acc, p3, v3);
        if (more) {
            kc0 = kn0; kc1 = kn1; kc2 = kn2; kc3 = kn3;
            ia0 = ib0; ia1 = ib1; ia2 = ib2; ia3 = ib3;
            if (more2) { ib0 = ic0; ib1 = ic1; ib2 = ic2; ib3 = ic3; }
        }
    }
    for (int i = s + nfull * 4; i < e; i++) {
        int s0 = g_csrsrc[i];
        uint4 k0 = *(const uint4*)(g_kh + (size_t)s0 * 128 + koff);
        uint4 v0 = *(const uint4*)(g_vh + (size_t)s0 * 128 + koff);
        float d0 = dot8h(q, k0);
#pragma unroll
        for (int r = 1; r <= 4; r <<= 1)
            d0 += __shfl_xor_sync(0xffffffffu, d0, r);
        float p0 = __expf(d0 * 0.125f);
        den += p0;
        acc8h(acc, p0, v0);
    }

    float inv = 0.25f * __fdividef(1.f, fmaxf(den, 1e-16f));
    float outv[8];
#pragma unroll
    for (int j = 0; j < 8; j++) {
        float ag = acc[j] * inv;
        ag += __shfl_xor_sync(0xffffffffu, ag, 8);
        ag += __shfl_xor_sync(0xffffffffu, ag, 16);
        outv[j] = ag;
    }
    int dbase = (l & 7) * 8;
    const float* skp = g_skip + (size_t)n * 64 + dbase;
    float4 s0f = *(const float4*)skp, s1f = *(const float4*)(skp + 4);
    float sk[8] = {s0f.x, s0f.y, s0f.z, s0f.w, s1f.x, s1f.y, s1f.z, s1f.w};
    float tv[8];
#pragma unroll
    for (int j = 0; j < 8; j++) tv[j] = ftanh(outv[j] + sk[j]);

    float p8[8];
#pragma unroll
    for (int o = 0; o < 8; o++) {
        const float* wr = sWm + o * 64 + dbase;
        float4 w0 = *(const float4*)wr, w1 = *(const float4*)(wr + 4);
        p8[o] = tv[0]*w0.x + tv[1]*w0.y + tv[2]*w0.z + tv[3]*w0.w
              + tv[4]*w1.x + tv[5]*w1.y + tv[6]*w1.z + tv[7]*w1.w;
    }
#pragma unroll
    for (int o = 0; o < 8; o++) {
        p8[o] += __shfl_xor_sync(0xffffffffu, p8[o], 1);
        p8[o] += __shfl_xor_sync(0xffffffffu, p8[o], 2);
        p8[o] += __shfl_xor_sync(0xffffffffu, p8[o], 4);
    }
    if (l < 8) g_theta[((size_t)(t + 1) * NN + n) * 8 + l] = p8[l];
    if (l == 0) {
        union { unsigned u; __half2 h; } c0, c1, c2, c3;
        c0.h = __floats2half2_rn(p8[0], p8[1]);
        c1.h = __floats2half2_rn(p8[2], p8[3]);
        c2.h = __floats2half2_rn(p8[4], p8[5]);
        c3.h = __floats2half2_rn(p8[6], p8[7]);
        *(uint4*)(g_thetah + (size_t)n * 4) = make_uint4(c0.u, c1.u, c2.u, c3.u);
    }
}

// ---------------- final postprocess ----------------------------------------
__global__ void k_post(float* __restrict__ out) {
    int idx = blockIdx.x * 256 + threadIdx.x;
    if (idx >= NN * TT) return;
    int n = idx / TT, t = idx - n * TT;
    const float* th = g_theta + ((size_t)(t + 1) * NN + n) * 8;
    float4 a0 = *(const float4*)th, a1 = *(const float4*)(th + 4);
    float v5 = a1.y, v6 = a1.z, v7 = a1.w;
    float s5 = 1.f / (1.f + expf(-v5));
    float s6 = 1.f / (1.f + expf(-v6));
    float a = s5 * s6;
    float b = s5 - a;
    float cpl = fmaxf(v7, 0.f) + log1pf(expf(-fabsf(v7)));
    float* op = out + ((size_t)n * TT + t) * 8;
    *(float4*)op       = make_float4(a0.x, a0.y, a0.z, a0.w);
    *(float4*)(op + 4) = make_float4(a1.x, a, b, cpl);
}

// ---------------- launch ----------------------------------------------------
extern "C" void kernel_launch(void* const* d_in, const int* in_sizes, int n_in,
                              void* d_out, int out_size) {
    const float* x    = (const float*)d_in[0];
    const int*   ei   = (const int*)d_in[1];
    const float* Wih  = (const float*)d_in[2];
    const float* Whh  = (const float*)d_in[3];
    const float* bih  = (const float*)d_in[4];
    const float* bhh  = (const float*)d_in[5];
    const float* Wq   = (const float*)d_in[6];
    const float* bq   = (const float*)d_in[7];
    const float* Wk   = (const float*)d_in[8];
    const float* bk   = (const float*)d_in[9];
    const float* Wv   = (const float*)d_in[10];
    const float* bv   = (const float*)d_in[11];
    const float* Wsk  = (const float*)d_in[12];
    const float* bsk  = (const float*)d_in[13];
    const float* Wmlp = (const float*)d_in[14];

    // 4th launch = k_pre -> ncu verifies the all-t precompute GEMM
    k_initwprep<<<170, 256>>>(Wq, bq, Wk, bk, Wv, bv, Wsk, bsk);
    k_xw<<<dim3(79, 100), 256>>>(x, Wih, bih, bhh);
    k_lstm2<<<(NN + 31) / 32, 256>>>(Whh);
    k_pre<<<dim3(13, (TT * NN + 127) / 128), 256>>>();
    k_count<<<(EE + 255) / 256, 256>>>(ei);
    k_scan<<<1, 256>>>();
    k_scatter<<<(EE + 255) / 256, 256>>>(ei);

    for (int t = 0; t < TT; t++) {
        k_qkv2<<<dim3(13, 40), 256>>>(t);
        k_edge<<<625, 256>>>(t, Wmlp);
    }
    k_post<<<(NN * TT + 255) / 256, 256>>>((float*)d_out);
}

// round 15
// speedup vs baseline: 1.2141x; 1.2141x over previous
#include <cuda_runtime.h>
#include <cuda_fp16.h>
#include <math.h>

#define NN 5000
#define TT 100
#define INDIM 32
#define FEAT 64
#define HIDD 64
#define OUTD 8
#define NHEADS 4
#define EE 160000
#define FIN 72
#define SSTR 88   // smem half stride (44 uints) for k_gemm tiles

// ---------------- scratch (device globals; POD types only) -----------------
__device__ unsigned int g_embh[(size_t)TT * NN * 32];         // fp16 emb [T][N][64]
__device__ unsigned int g_xw[(size_t)TT * NN * 128];          // fp16 x@Wih+b
__device__ unsigned int g_wh[13 * 64 * 44];                   // fp16 W chunks [c][n][k/2]
__device__ float        g_bias[13 * 64];
__device__ float        g_q[(size_t)NN * 256];                // fp32 q
__device__ float        g_skip[(size_t)NN * 64];              // fp32 skip
__device__ unsigned int g_kh[(size_t)NN * 128];               // fp16 k
__device__ unsigned int g_vh[(size_t)NN * 128];               // fp16 v
__device__ float        g_theta[(size_t)(TT + 1) * NN * OUTD];// fp32 theta history
__device__ unsigned int g_thetah[(size_t)NN * 4];             // fp16 theta (rolling)
__device__ int          g_cnt[NN];
__device__ int          g_rowptr[NN + 1];
__device__ int          g_cursor[NN];
__device__ int          g_csrsrc[EE];

__device__ __forceinline__ float fsig(float x) {
    return __fdividef(1.f, 1.f + __expf(-x));
}
__device__ __forceinline__ float ftanh(float x) {
    return 2.f * fsig(2.f * x) - 1.f;
}

__device__ __forceinline__ void mma16816(float* c, const unsigned* a, const unsigned* b) {
    asm volatile(
        "mma.sync.aligned.m16n8k16.row.col.f32.f16.f16.f32 "
        "{%0,%1,%2,%3}, {%4,%5,%6,%7}, {%8,%9}, {%0,%1,%2,%3};"
        : "+f"(c[0]), "+f"(c[1]), "+f"(c[2]), "+f"(c[3])
        : "r"(a[0]), "r"(a[1]), "r"(a[2]), "r"(a[3]), "r"(b[0]), "r"(b[1]));
}

// ---------------- fused init + weight prep ---------------------------------
__global__ void k_initwprep(const float* __restrict__ Wq, const float* __restrict__ bq,
                            const float* __restrict__ Wk, const float* __restrict__ bk,
                            const float* __restrict__ Wv, const float* __restrict__ bv,
                            const float* __restrict__ Wsk, const float* __restrict__ bsk) {
    int tid = threadIdx.x;
    if (blockIdx.x < 13) {
        int chunk = blockIdx.x;
        const float* Wsrc; const float* bsrc; int cofs, width;
        if (chunk < 4)       { Wsrc = Wq;  bsrc = bq;  cofs = chunk * 64;       width = 256; }
        else if (chunk < 8)  { Wsrc = Wk;  bsrc = bk;  cofs = (chunk - 4) * 64; width = 256; }
        else if (chunk < 12) { Wsrc = Wv;  bsrc = bv;  cofs = (chunk - 8) * 64; width = 256; }
        else                 { Wsrc = Wsk; bsrc = bsk; cofs = 0;                width = 64;  }
        for (int i = tid; i < 64 * 44; i += 256) {
            int n = i / 44, ku = i - n * 44;
            unsigned val = 0u;
            if (ku < 40) {
                int k0 = ku * 2, k1 = k0 + 1;
                float f0 = (k0 < 72) ? Wsrc[k0 * width + cofs + n] : 0.f;
                float f1 = (k1 < 72) ? Wsrc[k1 * width + cofs + n] : 0.f;
                union { unsigned u; __half2 h; } p; p.h = __floats2half2_rn(f0, f1);
                val = p.u;
            }
            g_wh[(chunk * 64 + n) * 44 + ku] = val;
        }
        if (tid < 64) g_bias[chunk * 64 + tid] = bsrc[cofs + tid];
    } else {
        int i = (blockIdx.x - 13) * 256 + tid;
        if (i < NN) g_cnt[i] = 0;
        if (i < NN * OUTD) g_theta[i] = 0.f;
        if (i < NN * 4) g_thetah[i] = 0u;
    }
}

// ---------------- CSR build ------------------------------------------------
__global__ void k_count(const int* __restrict__ ei) {
    int e = blockIdx.x * 256 + threadIdx.x;
    if (e < EE) atomicAdd(&g_cnt[ei[EE + e]], 1);
}

__global__ void k_scan() {
    __shared__ int ss[256];
    int tid = threadIdx.x;
    int i0 = tid * 20;
    int sum = 0;
    for (int i = i0; i < i0 + 20 && i < NN; i++) sum += g_cnt[i];
    ss[tid] = sum;
    __syncthreads();
    if (tid == 0) {
        int run = 0;
        for (int i = 0; i < 256; i++) { int v = ss[i]; ss[i] = run; run += v; }
    }
    __syncthreads();
    int run = ss[tid];
    for (int i = i0; i < i0 + 20 && i < NN; i++) {
        g_rowptr[i] = run;
        g_cursor[i] = run;
        run += g_cnt[i];
    }
    if (tid == 255) g_rowptr[NN] = run;
}

__global__ void k_scatter(const int* __restrict__ ei) {
    int e = blockIdx.x * 256 + threadIdx.x;
    if (e < EE) {
        int d = ei[EE + e];
        int pos = atomicAdd(&g_cursor[d], 1);
        g_csrsrc[pos] = ei[e];
    }
}

// ---------------- k_xw: XW = x @ Wih + bias (all t, HMMA) ------------------
__global__ void k_xw(const float* __restrict__ x, const float* __restrict__ Wih,
                     const float* __restrict__ bih, const float* __restrict__ bhh) {
    __shared__ __align__(16) __half sA[64 * 40];
    __shared__ __align__(16) __half sB[256 * 40];
    __shared__ float sBias[256];
    int tid = threadIdx.x;
    int nb0 = blockIdx.x * 64;
    int t = blockIdx.y;

    for (int i = tid; i < 64 * 32; i += 256) {
        int r = i >> 5, k = i & 31;
        int node = nb0 + r;
        float v = (node < NN) ? x[((size_t)node * TT + t) * 32 + k] : 0.f;
        sA[r * 40 + k] = __float2half(v);
    }
    for (int i = tid; i < 32 * 256; i += 256) {
        int n = i & 255, k = i >> 8;
        sB[n * 40 + k] = __float2half(Wih[k * 256 + n]);
    }
    sBias[tid] = bih[tid] + bhh[tid];
    __syncthreads();

    int wid = tid >> 5, l = tid & 31;
    int wr = wid >> 2, wc = wid & 3;
    int g = l >> 2, tg = l & 3;

    float acc[2][8][4] = {};
#pragma unroll
    for (int ks = 0; ks < 2; ks++) {
        int kb = ks * 16;
        unsigned a[2][4], b[8][2];
#pragma unroll
        for (int ms = 0; ms < 2; ms++) {
            int row = wr * 32 + ms * 16 + g;
            const __half* p0 = sA + row * 40 + kb + tg * 2;
            const __half* p1 = sA + (row + 8) * 40 + kb + tg * 2;
            a[ms][0] = *(const unsigned*)p0;
            a[ms][1] = *(const unsigned*)p1;
            a[ms][2] = *(const unsigned*)(p0 + 8);
            a[ms][3] = *(const unsigned*)(p1 + 8);
        }
#pragma unroll
        for (int ns = 0; ns < 8; ns++) {
            int n = wc * 64 + ns * 8 + g;
            const __half* p = sB + n * 40 + kb + tg * 2;
            b[ns][0] = *(const unsigned*)p;
            b[ns][1] = *(const unsigned*)(p + 8);
        }
#pragma unroll
        for (int ms = 0; ms < 2; ms++)
#pragma unroll
            for (int ns = 0; ns < 8; ns++)
                mma16816(acc[ms][ns], a[ms], b[ns]);
    }

#pragma unroll
    for (int ms = 0; ms < 2; ms++) {
        int row0 = nb0 + wr * 32 + ms * 16 + g;
#pragma unroll
        for (int ns = 0; ns < 8; ns++) {
            int col = wc * 64 + ns * 8 + tg * 2;
            float b0 = sBias[col], b1 = sBias[col + 1];
            union { unsigned u; __half2 h; } p0, p1;
            p0.h = __floats2half2_rn(acc[ms][ns][0] + b0, acc[ms][ns][1] + b1);
            p1.h = __floats2half2_rn(acc[ms][ns][2] + b0, acc[ms][ns][3] + b1);
            int cu = col >> 1;
            if (row0 < NN)     g_xw[((size_t)t * NN + row0) * 128 + cu] = p0.u;
            if (row0 + 8 < NN) g_xw[((size_t)t * NN + row0 + 8) * 128 + cu] = p1.u;
        }
    }
}

// ---------------- k_lstm2: HMMA recurrence, 32 nodes/block -----------------
__global__ void k_lstm2(const float* __restrict__ Whh) {
    __shared__ __align__(16) __half sBt[256 * 72];   // Whh^T [n][k]
    __shared__ __align__(16) __half sH[2 * 32 * 72]; // double-buffered h

    int tid = threadIdx.x;
    int nb0 = blockIdx.x * 32;

    for (int i = tid; i < 64 * 256; i += 256) {
        int n = i & 255, k = i >> 8;
        sBt[n * 72 + k] = __float2half(Whh[k * 256 + n]);
    }
    for (int i = tid; i < 32 * 72; i += 256) sH[i] = __float2half(0.f);

    int wid = tid >> 5, l = tid & 31;
    int wr = wid >> 2, wc = wid & 3;
    int g = l >> 2, tg = l & 3;

    int row0 = wr * 16 + g;
    int node0 = nb0 + row0, node1 = node0 + 8;
    bool v0 = node0 < NN, v1 = node1 < NN;

    float cst[8];
#pragma unroll
    for (int i = 0; i < 8; i++) cst[i] = 0.f;

    unsigned cur[16];
#pragma unroll
    for (int j = 0; j < 8; j++) {
        int colu = (wc + 4 * j) * 4 + tg;
        cur[j * 2]     = v0 ? g_xw[(size_t)node0 * 128 + colu] : 0u;
        cur[j * 2 + 1] = v1 ? g_xw[(size_t)node1 * 128 + colu] : 0u;
    }
    __syncthreads();

    for (int t = 0; t < TT; t++) {
        const __half* sHr = sH + (t & 1) * 32 * 72;
        __half* sHw = sH + ((t + 1) & 1) * 32 * 72;

        float acc[8][4];
#pragma unroll
        for (int j = 0; j < 8; j++) {
            union { unsigned u; __half2 h; } p0, p1;
            p0.u = cur[j * 2]; p1.u = cur[j * 2 + 1];
            float2 f0 = __half22float2(p0.h), f1 = __half22float2(p1.h);
            acc[j][0] = f0.x; acc[j][1] = f0.y;
            acc[j][2] = f1.x; acc[j][3] = f1.y;
        }
        if (t + 1 < TT) {
            size_t base = (size_t)(t + 1) * NN;
#pragma unroll
            for (int j = 0; j < 8; j++) {
                int colu = (wc + 4 * j) * 4 + tg;
                cur[j * 2]     = v0 ? g_xw[(base + node0) * 128 + colu] : 0u;
                cur[j * 2 + 1] = v1 ? g_xw[(base + node1) * 128 + colu] : 0u;
            }
        }

#pragma unroll
        for (int ks = 0; ks < 4; ks++) {
            int kb = ks * 16;
            unsigned a[4], b[8][2];
            const __half* p0 = sHr + row0 * 72 + kb + tg * 2;
            const __half* p1 = sHr + (row0 + 8) * 72 + kb + tg * 2;
            a[0] = *(const unsigned*)p0;
            a[1] = *(const unsigned*)p1;
            a[2] = *(const unsigned*)(p0 + 8);
            a[3] = *(const unsigned*)(p1 + 8);
#pragma unroll
            for (int j = 0; j < 8; j++) {
                int n = (wc + 4 * j) * 8 + g;
                const __half* p = sBt + n * 72 + kb + tg * 2;
                b[j][0] = *(const unsigned*)p;
                b[j][1] = *(const unsigned*)(p + 8);
            }
#pragma unroll
            for (int j = 0; j < 8; j++)
                mma16816(acc[j], a, b[j]);
        }

#pragma unroll
        for (int p = 0; p < 2; p++)
#pragma unroll
            for (int rh = 0; rh < 2; rh++) {
                int row = row0 + rh * 8;
                int node = nb0 + row;
                float hv[2];
#pragma unroll
                for (int ch = 0; ch < 2; ch++) {
                    int ri = rh * 2 + ch;
                    float iv = fsig(acc[p][ri]);
                    float fv = fsig(acc[2 + p][ri]);
                    float gv = ftanh(acc[4 + p][ri]);
                    float ov = fsig(acc[6 + p][ri]);
                    int ci = p * 4 + rh * 2 + ch;
                    cst[ci] = fv * cst[ci] + iv * gv;
                    hv[ch] = ov * ftanh(cst[ci]);
                }
                int d = wc * 8 + p * 32 + tg * 2;
                __half2 h2 = __floats2half2_rn(hv[0], hv[1]);
                *(__half2*)(sHw + row * 72 + d) = h2;
                if (node < NN) {
                    union { __half2 h; unsigned u; } cv; cv.h = h2;
                    g_embh[((size_t)t * NN + node) * 32 + (d >> 1)] = cv.u;
                }
            }
        __syncthreads();
    }
}

// ---------------- per-step GEMM: 2 chunks per block (H staged once) --------
// grid (7, 40): block x handles chunks {2x, 2x+1} (last block: chunk 12 only).
__global__ void k_gemm(int t) {
    __shared__ __align__(16) __half sA[128 * SSTR];        // 22528 B
    __shared__ __align__(16) __half sB2[2 * 64 * SSTR];    // 22528 B
    __shared__ float sBias[128];

    int chunk0 = blockIdx.x * 2;
    int nch = (chunk0 + 1 < 13) ? 2 : 1;
    int tid = threadIdx.x;
    int nb0 = blockIdx.y * 128;
    unsigned* sAu = (unsigned*)sA;
    unsigned* sBu = (unsigned*)sB2;

    for (int i = tid; i < 128 * 10; i += 256) {
        int r = i / 10, j = i - r * 10;
        int node = nb0 + r;
        uint4 v = make_uint4(0u, 0u, 0u, 0u);
        if (node < NN) {
            if (j < 8)      v = *(const uint4*)(g_embh + ((size_t)t * NN + node) * 32 + j * 4);
            else if (j == 8) v = *(const uint4*)(g_thetah + (size_t)node * 4);
        }
        *(uint4*)(sAu + r * 44 + j * 4) = v;
    }
    for (int i = tid; i < nch * 64 * 10; i += 256) {
        int c = i / 640, rem = i - c * 640;
        int n = rem / 10, j = rem - n * 10;
        *(uint4*)(sBu + c * 64 * 44 + n * 44 + j * 4) =
            *(const uint4*)(g_wh + (size_t)((chunk0 + c) * 64 + n) * 44 + j * 4);
    }
    if (tid < nch * 64) sBias[tid] = g_bias[chunk0 * 64 + tid];
    __syncthreads();

    int wid = tid >> 5, l = tid & 31;
    int wr = wid >> 1, wc = wid & 1;
    int g = l >> 2, tg = l & 3;

    for (int c = 0; c < nch; c++) {
        int chunk = chunk0 + c;
        const __half* sBt = sB2 + c * 64 * SSTR;
        float acc[2][4][4] = {};
#pragma unroll
        for (int ks = 0; ks < 5; ks++) {
            int kb = ks * 16;
            unsigned a[2][4], b[4][2];
#pragma unroll
            for (int ms = 0; ms < 2; ms++) {
                int row = wr * 32 + ms * 16 + g;
                const __half* p0 = sA + row * SSTR + kb + tg * 2;
                const __half* p1 = sA + (row + 8) * SSTR + kb + tg * 2;
                a[ms][0] = *(const unsigned*)p0;
                a[ms][1] = *(const unsigned*)p1;
                a[ms][2] = *(const unsigned*)(p0 + 8);
                a[ms][3] = *(const unsigned*)(p1 + 8);
            }
#pragma unroll
            for (int ns = 0; ns < 4; ns++) {
                int n = wc * 32 + ns * 8 + g;
                const __half* p = sBt + n * SSTR + kb + tg * 2;
                b[ns][0] = *(const unsigned*)p;
                b[ns][1] = *(const unsigned*)(p + 8);
            }
#pragma unroll
            for (int ms = 0; ms < 2; ms++)
#pragma unroll
                for (int ns = 0; ns < 4; ns++)
                    mma16816(acc[ms][ns], a[ms], b[ns]);
        }

#pragma unroll
        for (int ms = 0; ms < 2; ms++) {
            int row0 = nb0 + wr * 32 + ms * 16 + g;
#pragma unroll
            for (int ns = 0; ns < 4; ns++) {
                int col = wc * 32 + ns * 8 + tg * 2;
                float b0 = sBias[c * 64 + col], b1 = sBias[c * 64 + col + 1];
                float o0 = acc[ms][ns][0] + b0, o1 = acc[ms][ns][1] + b1;
                float o2 = acc[ms][ns][2] + b0, o3 = acc[ms][ns][3] + b1;
                if (chunk < 4) {
                    if (row0 < NN)
                        *(float2*)(g_q + (size_t)row0 * 256 + chunk * 64 + col) = make_float2(o0, o1);
                    if (row0 + 8 < NN)
                        *(float2*)(g_q + (size_t)(row0 + 8) * 256 + chunk * 64 + col) = make_float2(o2, o3);
                } else if (chunk < 12) {
                    unsigned int* base = (chunk < 8) ? g_kh : g_vh;
                    int cofs2 = ((chunk < 8) ? (chunk - 4) : (chunk - 8)) * 32 + (col >> 1);
                    union { unsigned u; __half2 h; } p0, p1;
                    p0.h = __floats2half2_rn(o0, o1);
                    p1.h = __floats2half2_rn(o2, o3);
                    if (row0 < NN)     base[(size_t)row0 * 128 + cofs2] = p0.u;
                    if (row0 + 8 < NN) base[(size_t)(row0 + 8) * 128 + cofs2] = p1.u;
                } else {
                    if (row0 < NN)
                        *(float2*)(g_skip + (size_t)row0 * 64 + col) = make_float2(o0, o1);
                    if (row0 + 8 < NN)
                        *(float2*)(g_skip + (size_t)(row0 + 8) * 64 + col) = make_float2(o2, o3);
                }
            }
        }
    }
}

// ---------------- per-step edge attention + epilogue -----------------------
__device__ __forceinline__ float dot8h(const float* q, uint4 r) {
    union { uint4 u; __half2 h[4]; } pk; pk.u = r;
    float2 f0 = __half22float2(pk.h[0]);
    float2 f1 = __half22float2(pk.h[1]);
    float2 f2 = __half22float2(pk.h[2]);
    float2 f3 = __half22float2(pk.h[3]);
    return q[0]*f0.x + q[1]*f0.y + q[2]*f1.x + q[3]*f1.y
         + q[4]*f2.x + q[5]*f2.y + q[6]*f3.x + q[7]*f3.y;
}
__device__ __forceinline__ void acc8h(float* acc, float p, uint4 r) {
    union { uint4 u; __half2 h[4]; } pk; pk.u = r;
    float2 f0 = __half22float2(pk.h[0]);
    float2 f1 = __half22float2(pk.h[1]);
    float2 f2 = __half22float2(pk.h[2]);
    float2 f3 = __half22float2(pk.h[3]);
    acc[0] += p * f0.x; acc[1] += p * f0.y;
    acc[2] += p * f1.x; acc[3] += p * f1.y;
    acc[4] += p * f2.x; acc[5] += p * f2.y;
    acc[6] += p * f3.x; acc[7] += p * f3.y;
}

__global__ void k_edge(int t, const float* __restrict__ Wmlp) {
    __shared__ float sWm[8 * 64];
    int tid = threadIdx.x;
    for (int i = tid; i < 512; i += 256) {
        int d = i >> 3, o = i & 7;
        sWm[o * 64 + d] = Wmlp[i];
    }
    __syncthreads();

    int wid = tid >> 5, l = tid & 31;
    int n = blockIdx.x * 8 + wid;

    float q[8];
    {
        const float* qp = g_q + (size_t)n * 256 + l * 8;
        float4 q0 = __ldg((const float4*)qp);
        float4 q1 = __ldg((const float4*)(qp + 4));
        q[0]=q0.x; q[1]=q0.y; q[2]=q0.z; q[3]=q0.w;
        q[4]=q1.x; q[5]=q1.y; q[6]=q1.z; q[7]=q1.w;
    }
    int s = __ldg(&g_rowptr[n]), e = __ldg(&g_rowptr[n + 1]);
    float den = 0.f;
    float acc[8] = {};
    int koff = l * 4;

    // software-pipelined batches of 4: indices prefetched one batch ahead
    int nfull = (e - s) >> 2;
    int i4 = s;
    int nidx0, nidx1, nidx2, nidx3;
    if (nfull > 0) {
        nidx0 = __ldg(&g_csrsrc[i4]);     nidx1 = __ldg(&g_csrsrc[i4 + 1]);
        nidx2 = __ldg(&g_csrsrc[i4 + 2]); nidx3 = __ldg(&g_csrsrc[i4 + 3]);
    }
    for (int b = 0; b < nfull; b++) {
        int s0 = nidx0, s1 = nidx1, s2 = nidx2, s3 = nidx3;
        uint4 k0 = __ldg((const uint4*)(g_kh + (size_t)s0 * 128 + koff));
        uint4 k1 = __ldg((const uint4*)(g_kh + (size_t)s1 * 128 + koff));
        uint4 k2 = __ldg((const uint4*)(g_kh + (size_t)s2 * 128 + koff));
        uint4 k3 = __ldg((const uint4*)(g_kh + (size_t)s3 * 128 + koff));
        uint4 v0 = __ldg((const uint4*)(g_vh + (size_t)s0 * 128 + koff));
        uint4 v1 = __ldg((const uint4*)(g_vh + (size_t)s1 * 128 + koff));
        uint4 v2 = __ldg((const uint4*)(g_vh + (size_t)s2 * 128 + koff));
        uint4 v3 = __ldg((const uint4*)(g_vh + (size_t)s3 * 128 + koff));
        i4 += 4;
        if (b + 1 < nfull) {
            nidx0 = __ldg(&g_csrsrc[i4]);     nidx1 = __ldg(&g_csrsrc[i4 + 1]);
            nidx2 = __ldg(&g_csrsrc[i4 + 2]); nidx3 = __ldg(&g_csrsrc[i4 + 3]);
        }
        float d0 = dot8h(q, k0), d1 = dot8h(q, k1);
        float d2 = dot8h(q, k2), d3 = dot8h(q, k3);
#pragma unroll
        for (int r = 1; r <= 4; r <<= 1) {
            d0 += __shfl_xor_sync(0xffffffffu, d0, r);
            d1 += __shfl_xor_sync(0xffffffffu, d1, r);
            d2 += __shfl_xor_sync(0xffffffffu, d2, r);
            d3 += __shfl_xor_sync(0xffffffffu, d3, r);
        }
        float p0 = __expf(d0 * 0.125f), p1 = __expf(d1 * 0.125f);
        float p2 = __expf(d2 * 0.125f), p3 = __expf(d3 * 0.125f);
        den += (p0 + p1) + (p2 + p3);
        acc8h(acc, p0, v0); acc8h(acc, p1, v1);
        acc8h(acc, p2, v2); acc8h(acc, p3, v3);
    }
    for (int i = i4; i < e; i++) {
        int s0 = __ldg(&g_csrsrc[i]);
        uint4 k0 = __ldg((const uint4*)(g_kh + (size_t)s0 * 128 + koff));
        uint4 v0 = __ldg((const uint4*)(g_vh + (size_t)s0 * 128 + koff));
        float d0 = dot8h(q, k0);
#pragma unroll
        for (int r = 1; r <= 4; r <<= 1)
            d0 += __shfl_xor_sync(0xffffffffu, d0, r);
        float p0 = __expf(d0 * 0.125f);
        den += p0;
        acc8h(acc, p0, v0);
    }

    float inv = 0.25f * __fdividef(1.f, fmaxf(den, 1e-16f));
    float outv[8];
#pragma unroll
    for (int j = 0; j < 8; j++) {
        float ag = acc[j] * inv;
        ag += __shfl_xor_sync(0xffffffffu, ag, 8);
        ag += __shfl_xor_sync(0xffffffffu, ag, 16);
        outv[j] = ag;
    }
    int dbase = (l & 7) * 8;
    const float* skp = g_skip + (size_t)n * 64 + dbase;
    float4 s0f = __ldg((const float4*)skp);
    float4 s1f = __ldg((const float4*)(skp + 4));
    float sk[8] = {s0f.x, s0f.y, s0f.z, s0f.w, s1f.x, s1f.y, s1f.z, s1f.w};
    float tv[8];
#pragma unroll
    for (int j = 0; j < 8; j++) tv[j] = ftanh(outv[j] + sk[j]);

    float p8[8];
#pragma unroll
    for (int o = 0; o < 8; o++) {
        const float* wr = sWm + o * 64 + dbase;
        float4 w0 = *(const float4*)wr, w1 = *(const float4*)(wr + 4);
        p8[o] = tv[0]*w0.x + tv[1]*w0.y + tv[2]*w0.z + tv[3]*w0.w
              + tv[4]*w1.x + tv[5]*w1.y + tv[6]*w1.z + tv[7]*w1.w;
    }
#pragma unroll
    for (int o = 0; o < 8; o++) {
        p8[o] += __shfl_xor_sync(0xffffffffu, p8[o], 1);
        p8[o] += __shfl_xor_sync(0xffffffffu, p8[o], 2);
        p8[o] += __shfl_xor_sync(0xffffffffu, p8[o], 4);
    }
    if (l < 8) g_theta[((size_t)(t + 1) * NN + n) * 8 + l] = p8[l];
    if (l == 0) {
        union { unsigned u; __half2 h; } c0, c1, c2, c3;
        c0.h = __floats2half2_rn(p8[0], p8[1]);
        c1.h = __floats2half2_rn(p8[2], p8[3]);
        c2.h = __floats2half2_rn(p8[4], p8[5]);
        c3.h = __floats2half2_rn(p8[6], p8[7]);
        *(uint4*)(g_thetah + (size_t)n * 4) = make_uint4(c0.u, c1.u, c2.u, c3.u);
    }
}

// ---------------- final postprocess ----------------------------------------
__global__ void k_post(float* __restrict__ out) {
    int idx = blockIdx.x * 256 + threadIdx.x;
    if (idx >= NN * TT) return;
    int n = idx / TT, t = idx - n * TT;
    const float* th = g_theta + ((size_t)(t + 1) * NN + n) * 8;
    float4 a0 = *(const float4*)th, a1 = *(const float4*)(th + 4);
    float v5 = a1.y, v6 = a1.z, v7 = a1.w;
    float s5 = 1.f / (1.f + expf(-v5));
    float s6 = 1.f / (1.f + expf(-v6));
    float a = s5 * s6;
    float b = s5 - a;
    float cpl = fmaxf(v7, 0.f) + log1pf(expf(-fabsf(v7)));
    float* op = out + ((size_t)n * TT + t) * 8;
    *(float4*)op       = make_float4(a0.x, a0.y, a0.z, a0.w);
    *(float4*)(op + 4) = make_float4(a1.x, a, b, cpl);
}

// ---------------- launch ----------------------------------------------------
extern "C" void kernel_launch(void* const* d_in, const int* in_sizes, int n_in,
                              void* d_out, int out_size) {
    const float* x    = (const float*)d_in[0];
    const int*   ei   = (const int*)d_in[1];
    const float* Wih  = (const float*)d_in[2];
    const float* Whh  = (const float*)d_in[3];
    const float* bih  = (const float*)d_in[4];
    const float* bhh  = (const float*)d_in[5];
    const float* Wq   = (const float*)d_in[6];
    const float* bq   = (const float*)d_in[7];
    const float* Wk   = (const float*)d_in[8];
    const float* bk   = (const float*)d_in[9];
    const float* Wv   = (const float*)d_in[10];
    const float* bv   = (const float*)d_in[11];
    const float* Wsk  = (const float*)d_in[12];
    const float* bsk  = (const float*)d_in[13];
    const float* Wmlp = (const float*)d_in[14];

    // 4th launch = k_gemm(0) -> ncu verifies the chunk-paired GEMM
    k_initwprep<<<170, 256>>>(Wq, bq, Wk, bk, Wv, bv, Wsk, bsk);
    k_xw<<<dim3(79, 100), 256>>>(x, Wih, bih, bhh);
    k_lstm2<<<(NN + 31) / 32, 256>>>(Whh);
    k_gemm<<<dim3(7, 40), 256>>>(0);
    k_count<<<(EE + 255) / 256, 256>>>(ei);
    k_scan<<<1, 256>>>();
    k_scatter<<<(EE + 255) / 256, 256>>>(ei);
    k_edge<<<625, 256>>>(0, Wmlp);

    for (int t = 1; t < TT; t++) {
        k_gemm<<<dim3(7, 40), 256>>>(t);
        k_edge<<<625, 256>>>(t, Wmlp);
    }
    k_post<<<(NN * TT + 255) / 256, 256>>>((float*)d_out);
}

// round 16
// speedup vs baseline: 1.2536x; 1.0325x over previous
#include <cuda_runtime.h>
#include <cuda_fp16.h>
#include <math.h>

#define NN 5000
#define TT 100
#define INDIM 32
#define FEAT 64
#define HIDD 64
#define OUTD 8
#define NHEADS 4
#define EE 160000
#define FIN 72
#define SSTR 88   // smem half stride (44 uints) for k_gemm tiles

// ---------------- scratch (device globals; POD types only) -----------------
__device__ unsigned int g_embh[(size_t)TT * NN * 32];         // fp16 emb [T][N][64]
__device__ unsigned int g_xw[(size_t)TT * NN * 128];          // fp16 x@Wih+b
__device__ unsigned int g_wh[13 * 64 * 44];                   // fp16 W chunks [c][n][k/2]
__device__ float        g_bias[13 * 64];
__device__ float        g_q[(size_t)NN * 256];                // fp32 q
__device__ float        g_skip[(size_t)NN * 64];              // fp32 skip
__device__ unsigned int g_kh[(size_t)NN * 128];               // fp16 k
__device__ unsigned int g_vh[(size_t)NN * 128];               // fp16 v
__device__ float        g_theta[(size_t)(TT + 1) * NN * OUTD];// fp32 theta history
__device__ unsigned int g_thetah[(size_t)NN * 4];             // fp16 theta (rolling)
__device__ int          g_cnt[NN];
__device__ int          g_rowptr[NN + 1];
__device__ int          g_cursor[NN];
__device__ int          g_csrsrc[EE];

__device__ __forceinline__ float fsig(float x) {
    return __fdividef(1.f, 1.f + __expf(-x));
}
__device__ __forceinline__ float ftanh(float x) {
    return 2.f * fsig(2.f * x) - 1.f;
}

__device__ __forceinline__ void mma16816(float* c, const unsigned* a, const unsigned* b) {
    asm volatile(
        "mma.sync.aligned.m16n8k16.row.col.f32.f16.f16.f32 "
        "{%0,%1,%2,%3}, {%4,%5,%6,%7}, {%8,%9}, {%0,%1,%2,%3};"
        : "+f"(c[0]), "+f"(c[1]), "+f"(c[2]), "+f"(c[3])
        : "r"(a[0]), "r"(a[1]), "r"(a[2]), "r"(a[3]), "r"(b[0]), "r"(b[1]));
}

// ---------------- fused init + weight prep ---------------------------------
__global__ void k_initwprep(const float* __restrict__ Wq, const float* __restrict__ bq,
                            const float* __restrict__ Wk, const float* __restrict__ bk,
                            const float* __restrict__ Wv, const float* __restrict__ bv,
                            const float* __restrict__ Wsk, const float* __restrict__ bsk) {
    int tid = threadIdx.x;
    if (blockIdx.x < 13) {
        int chunk = blockIdx.x;
        const float* Wsrc; const float* bsrc; int cofs, width;
        if (chunk < 4)       { Wsrc = Wq;  bsrc = bq;  cofs = chunk * 64;       width = 256; }
        else if (chunk < 8)  { Wsrc = Wk;  bsrc = bk;  cofs = (chunk - 4) * 64; width = 256; }
        else if (chunk < 12) { Wsrc = Wv;  bsrc = bv;  cofs = (chunk - 8) * 64; width = 256; }
        else                 { Wsrc = Wsk; bsrc = bsk; cofs = 0;                width = 64;  }
        for (int i = tid; i < 64 * 44; i += 256) {
            int n = i / 44, ku = i - n * 44;
            unsigned val = 0u;
            if (ku < 40) {
                int k0 = ku * 2, k1 = k0 + 1;
                float f0 = (k0 < 72) ? Wsrc[k0 * width + cofs + n] : 0.f;
                float f1 = (k1 < 72) ? Wsrc[k1 * width + cofs + n] : 0.f;
                union { unsigned u; __half2 h; } p; p.h = __floats2half2_rn(f0, f1);
                val = p.u;
            }
            g_wh[(chunk * 64 + n) * 44 + ku] = val;
        }
        if (tid < 64) g_bias[chunk * 64 + tid] = bsrc[cofs + tid];
    } else {
        int i = (blockIdx.x - 13) * 256 + tid;
        if (i < NN) g_cnt[i] = 0;
        if (i < NN * OUTD) g_theta[i] = 0.f;
        if (i < NN * 4) g_thetah[i] = 0u;
    }
}

// ---------------- CSR build ------------------------------------------------
__global__ void k_count(const int* __restrict__ ei) {
    int e = blockIdx.x * 256 + threadIdx.x;
    if (e < EE) atomicAdd(&g_cnt[ei[EE + e]], 1);
}

__global__ void k_scan() {
    __shared__ int ss[256];
    int tid = threadIdx.x;
    int i0 = tid * 20;
    int sum = 0;
    for (int i = i0; i < i0 + 20 && i < NN; i++) sum += g_cnt[i];
    ss[tid] = sum;
    __syncthreads();
    if (tid == 0) {
        int run = 0;
        for (int i = 0; i < 256; i++) { int v = ss[i]; ss[i] = run; run += v; }
    }
    __syncthreads();
    int run = ss[tid];
    for (int i = i0; i < i0 + 20 && i < NN; i++) {
        g_rowptr[i] = run;
        g_cursor[i] = run;
        run += g_cnt[i];
    }
    if (tid == 255) g_rowptr[NN] = run;
}

__global__ void k_scatter(const int* __restrict__ ei) {
    int e = blockIdx.x * 256 + threadIdx.x;
    if (e < EE) {
        int d = ei[EE + e];
        int pos = atomicAdd(&g_cursor[d], 1);
        g_csrsrc[pos] = ei[e];
    }
}

// ---------------- k_xw: XW = x @ Wih + bias (all t, HMMA) ------------------
__global__ void k_xw(const float* __restrict__ x, const float* __restrict__ Wih,
                     const float* __restrict__ bih, const float* __restrict__ bhh) {
    __shared__ __align__(16) __half sA[64 * 40];
    __shared__ __align__(16) __half sB[256 * 40];
    __shared__ float sBias[256];
    int tid = threadIdx.x;
    int nb0 = blockIdx.x * 64;
    int t = blockIdx.y;

    for (int i = tid; i < 64 * 32; i += 256) {
        int r = i >> 5, k = i & 31;
        int node = nb0 + r;
        float v = (node < NN) ? x[((size_t)node * TT + t) * 32 + k] : 0.f;
        sA[r * 40 + k] = __float2half(v);
    }
    for (int i = tid; i < 32 * 256; i += 256) {
        int n = i & 255, k = i >> 8;
        sB[n * 40 + k] = __float2half(Wih[k * 256 + n]);
    }
    sBias[tid] = bih[tid] + bhh[tid];
    __syncthreads();

    int wid = tid >> 5, l = tid & 31;
    int wr = wid >> 2, wc = wid & 3;
    int g = l >> 2, tg = l & 3;

    float acc[2][8][4] = {};
#pragma unroll
    for (int ks = 0; ks < 2; ks++) {
        int kb = ks * 16;
        unsigned a[2][4], b[8][2];
#pragma unroll
        for (int ms = 0; ms < 2; ms++) {
            int row = wr * 32 + ms * 16 + g;
            const __half* p0 = sA + row * 40 + kb + tg * 2;
            const __half* p1 = sA + (row + 8) * 40 + kb + tg * 2;
            a[ms][0] = *(const unsigned*)p0;
            a[ms][1] = *(const unsigned*)p1;
            a[ms][2] = *(const unsigned*)(p0 + 8);
            a[ms][3] = *(const unsigned*)(p1 + 8);
        }
#pragma unroll
        for (int ns = 0; ns < 8; ns++) {
            int n = wc * 64 + ns * 8 + g;
            const __half* p = sB + n * 40 + kb + tg * 2;
            b[ns][0] = *(const unsigned*)p;
            b[ns][1] = *(const unsigned*)(p + 8);
        }
#pragma unroll
        for (int ms = 0; ms < 2; ms++)
#pragma unroll
            for (int ns = 0; ns < 8; ns++)
                mma16816(acc[ms][ns], a[ms], b[ns]);
    }

#pragma unroll
    for (int ms = 0; ms < 2; ms++) {
        int row0 = nb0 + wr * 32 + ms * 16 + g;
#pragma unroll
        for (int ns = 0; ns < 8; ns++) {
            int col = wc * 64 + ns * 8 + tg * 2;
            float b0 = sBias[col], b1 = sBias[col + 1];
            union { unsigned u; __half2 h; } p0, p1;
            p0.h = __floats2half2_rn(acc[ms][ns][0] + b0, acc[ms][ns][1] + b1);
            p1.h = __floats2half2_rn(acc[ms][ns][2] + b0, acc[ms][ns][3] + b1);
            int cu = col >> 1;
            if (row0 < NN)     g_xw[((size_t)t * NN + row0) * 128 + cu] = p0.u;
            if (row0 + 8 < NN) g_xw[((size_t)t * NN + row0 + 8) * 128 + cu] = p1.u;
        }
    }
}

// ---------------- k_lstm2: HMMA recurrence, 32 nodes/block -----------------
__global__ void k_lstm2(const float* __restrict__ Whh) {
    __shared__ __align__(16) __half sBt[256 * 72];   // Whh^T [n][k]
    __shared__ __align__(16) __half sH[2 * 32 * 72]; // double-buffered h

    int tid = threadIdx.x;
    int nb0 = blockIdx.x * 32;

    for (int i = tid; i < 64 * 256; i += 256) {
        int n = i & 255, k = i >> 8;
        sBt[n * 72 + k] = __float2half(Whh[k * 256 + n]);
    }
    for (int i = tid; i < 32 * 72; i += 256) sH[i] = __float2half(0.f);

    int wid = tid >> 5, l = tid & 31;
    int wr = wid >> 2, wc = wid & 3;
    int g = l >> 2, tg = l & 3;

    int row0 = wr * 16 + g;
    int node0 = nb0 + row0, node1 = node0 + 8;
    bool v0 = node0 < NN, v1 = node1 < NN;

    float cst[8];
#pragma unroll
    for (int i = 0; i < 8; i++) cst[i] = 0.f;

    unsigned cur[16];
#pragma unroll
    for (int j = 0; j < 8; j++) {
        int colu = (wc + 4 * j) * 4 + tg;
        cur[j * 2]     = v0 ? g_xw[(size_t)node0 * 128 + colu] : 0u;
        cur[j * 2 + 1] = v1 ? g_xw[(size_t)node1 * 128 + colu] : 0u;
    }
    __syncthreads();

    for (int t = 0; t < TT; t++) {
        const __half* sHr = sH + (t & 1) * 32 * 72;
        __half* sHw = sH + ((t + 1) & 1) * 32 * 72;

        float acc[8][4];
#pragma unroll
        for (int j = 0; j < 8; j++) {
            union { unsigned u; __half2 h; } p0, p1;
            p0.u = cur[j * 2]; p1.u = cur[j * 2 + 1];
            float2 f0 = __half22float2(p0.h), f1 = __half22float2(p1.h);
            acc[j][0] = f0.x; acc[j][1] = f0.y;
            acc[j][2] = f1.x; acc[j][3] = f1.y;
        }
        if (t + 1 < TT) {
            size_t base = (size_t)(t + 1) * NN;
#pragma unroll
            for (int j = 0; j < 8; j++) {
                int colu = (wc + 4 * j) * 4 + tg;
                cur[j * 2]     = v0 ? g_xw[(base + node0) * 128 + colu] : 0u;
                cur[j * 2 + 1] = v1 ? g_xw[(base + node1) * 128 + colu] : 0u;
            }
        }

#pragma unroll
        for (int ks = 0; ks < 4; ks++) {
            int kb = ks * 16;
            unsigned a[4], b[8][2];
            const __half* p0 = sHr + row0 * 72 + kb + tg * 2;
            const __half* p1 = sHr + (row0 + 8) * 72 + kb + tg * 2;
            a[0] = *(const unsigned*)p0;
            a[1] = *(const unsigned*)p1;
            a[2] = *(const unsigned*)(p0 + 8);
            a[3] = *(const unsigned*)(p1 + 8);
#pragma unroll
            for (int j = 0; j < 8; j++) {
                int n = (wc + 4 * j) * 8 + g;
                const __half* p = sBt + n * 72 + kb + tg * 2;
                b[j][0] = *(const unsigned*)p;
                b[j][1] = *(const unsigned*)(p + 8);
            }
#pragma unroll
            for (int j = 0; j < 8; j++)
                mma16816(acc[j], a, b[j]);
        }

#pragma unroll
        for (int p = 0; p < 2; p++)
#pragma unroll
            for (int rh = 0; rh < 2; rh++) {
                int row = row0 + rh * 8;
                int node = nb0 + row;
                float hv[2];
#pragma unroll
                for (int ch = 0; ch < 2; ch++) {
                    int ri = rh * 2 + ch;
                    float iv = fsig(acc[p][ri]);
                    float fv = fsig(acc[2 + p][ri]);
                    float gv = ftanh(acc[4 + p][ri]);
                    float ov = fsig(acc[6 + p][ri]);
                    int ci = p * 4 + rh * 2 + ch;
                    cst[ci] = fv * cst[ci] + iv * gv;
                    hv[ch] = ov * ftanh(cst[ci]);
                }
                int d = wc * 8 + p * 32 + tg * 2;
                __half2 h2 = __floats2half2_rn(hv[0], hv[1]);
                *(__half2*)(sHw + row * 72 + d) = h2;
                if (node < NN) {
                    union { __half2 h; unsigned u; } cv; cv.h = h2;
                    g_embh[((size_t)t * NN + node) * 32 + (d >> 1)] = cv.u;
                }
            }
        __syncthreads();
    }
}

// ---------------- per-step GEMM: 2 chunks per block (H staged once) --------
__global__ void k_gemm(int t) {
    __shared__ __align__(16) __half sA[128 * SSTR];
    __shared__ __align__(16) __half sB2[2 * 64 * SSTR];
    __shared__ float sBias[128];

    int chunk0 = blockIdx.x * 2;
    int nch = (chunk0 + 1 < 13) ? 2 : 1;
    int tid = threadIdx.x;
    int nb0 = blockIdx.y * 128;
    unsigned* sAu = (unsigned*)sA;
    unsigned* sBu = (unsigned*)sB2;

    for (int i = tid; i < 128 * 10; i += 256) {
        int r = i / 10, j = i - r * 10;
        int node = nb0 + r;
        uint4 v = make_uint4(0u, 0u, 0u, 0u);
        if (node < NN) {
            if (j < 8)      v = *(const uint4*)(g_embh + ((size_t)t * NN + node) * 32 + j * 4);
            else if (j == 8) v = *(const uint4*)(g_thetah + (size_t)node * 4);
        }
        *(uint4*)(sAu + r * 44 + j * 4) = v;
    }
    for (int i = tid; i < nch * 64 * 10; i += 256) {
        int c = i / 640, rem = i - c * 640;
        int n = rem / 10, j = rem - n * 10;
        *(uint4*)(sBu + c * 64 * 44 + n * 44 + j * 4) =
            *(const uint4*)(g_wh + (size_t)((chunk0 + c) * 64 + n) * 44 + j * 4);
    }
    if (tid < nch * 64) sBias[tid] = g_bias[chunk0 * 64 + tid];
    __syncthreads();

    int wid = tid >> 5, l = tid & 31;
    int wr = wid >> 1, wc = wid & 1;
    int g = l >> 2, tg = l & 3;

    for (int c = 0; c < nch; c++) {
        int chunk = chunk0 + c;
        const __half* sBt = sB2 + c * 64 * SSTR;
        float acc[2][4][4] = {};
#pragma unroll
        for (int ks = 0; ks < 5; ks++) {
            int kb = ks * 16;
            unsigned a[2][4], b[4][2];
#pragma unroll
            for (int ms = 0; ms < 2; ms++) {
                int row = wr * 32 + ms * 16 + g;
                const __half* p0 = sA + row * SSTR + kb + tg * 2;
                const __half* p1 = sA + (row + 8) * SSTR + kb + tg * 2;
                a[ms][0] = *(const unsigned*)p0;
                a[ms][1] = *(const unsigned*)p1;
                a[ms][2] = *(const unsigned*)(p0 + 8);
                a[ms][3] = *(const unsigned*)(p1 + 8);
            }
#pragma unroll
            for (int ns = 0; ns < 4; ns++) {
                int n = wc * 32 + ns * 8 + g;
                const __half* p = sBt + n * SSTR + kb + tg * 2;
                b[ns][0] = *(const unsigned*)p;
                b[ns][1] = *(const unsigned*)(p + 8);
            }
#pragma unroll
            for (int ms = 0; ms < 2; ms++)
#pragma unroll
                for (int ns = 0; ns < 4; ns++)
                    mma16816(acc[ms][ns], a[ms], b[ns]);
        }

#pragma unroll
        for (int ms = 0; ms < 2; ms++) {
            int row0 = nb0 + wr * 32 + ms * 16 + g;
#pragma unroll
            for (int ns = 0; ns < 4; ns++) {
                int col = wc * 32 + ns * 8 + tg * 2;
                float b0 = sBias[c * 64 + col], b1 = sBias[c * 64 + col + 1];
                float o0 = acc[ms][ns][0] + b0, o1 = acc[ms][ns][1] + b1;
                float o2 = acc[ms][ns][2] + b0, o3 = acc[ms][ns][3] + b1;
                if (chunk < 4) {
                    if (row0 < NN)
                        *(float2*)(g_q + (size_t)row0 * 256 + chunk * 64 + col) = make_float2(o0, o1);
                    if (row0 + 8 < NN)
                        *(float2*)(g_q + (size_t)(row0 + 8) * 256 + chunk * 64 + col) = make_float2(o2, o3);
                } else if (chunk < 12) {
                    unsigned int* base = (chunk < 8) ? g_kh : g_vh;
                    int cofs2 = ((chunk < 8) ? (chunk - 4) : (chunk - 8)) * 32 + (col >> 1);
                    union { unsigned u; __half2 h; } p0, p1;
                    p0.h = __floats2half2_rn(o0, o1);
                    p1.h = __floats2half2_rn(o2, o3);
                    if (row0 < NN)     base[(size_t)row0 * 128 + cofs2] = p0.u;
                    if (row0 + 8 < NN) base[(size_t)(row0 + 8) * 128 + cofs2] = p1.u;
                } else {
                    if (row0 < NN)
                        *(float2*)(g_skip + (size_t)row0 * 64 + col) = make_float2(o0, o1);
                    if (row0 + 8 < NN)
                        *(float2*)(g_skip + (size_t)(row0 + 8) * 64 + col) = make_float2(o2, o3);
                }
            }
        }
    }
}

// ---------------- per-step edge attention: 2 warps per node ----------------
__device__ __forceinline__ float dot8h(const float* q, uint4 r) {
    union { uint4 u; __half2 h[4]; } pk; pk.u = r;
    float2 f0 = __half22float2(pk.h[0]);
    float2 f1 = __half22float2(pk.h[1]);
    float2 f2 = __half22float2(pk.h[2]);
    float2 f3 = __half22float2(pk.h[3]);
    return q[0]*f0.x + q[1]*f0.y + q[2]*f1.x + q[3]*f1.y
         + q[4]*f2.x + q[5]*f2.y + q[6]*f3.x + q[7]*f3.y;
}
__device__ __forceinline__ void acc8h(float* acc, float p, uint4 r) {
    union { uint4 u; __half2 h[4]; } pk; pk.u = r;
    float2 f0 = __half22float2(pk.h[0]);
    float2 f1 = __half22float2(pk.h[1]);
    float2 f2 = __half22float2(pk.h[2]);
    float2 f3 = __half22float2(pk.h[3]);
    acc[0] += p * f0.x; acc[1] += p * f0.y;
    acc[2] += p * f1.x; acc[3] += p * f1.y;
    acc[4] += p * f2.x; acc[5] += p * f2.y;
    acc[6] += p * f3.x; acc[7] += p * f3.y;
}

// grid 1250 x 256 thr: 4 nodes/block, warp pair (half 0/1) splits edge list.
__global__ void k_edge(int t, const float* __restrict__ Wmlp) {
    __shared__ float sWm[8 * 64];
    __shared__ float sPart[4][32][8];   // half-1 partial acc
    __shared__ float sDen[4][32];       // half-1 partial den
    int tid = threadIdx.x;
    for (int i = tid; i < 512; i += 256) {
        int d = i >> 3, o = i & 7;
        sWm[o * 64 + d] = Wmlp[i];
    }
    __syncthreads();

    int wid = tid >> 5, l = tid & 31;
    int nl = wid >> 1, half = wid & 1;
    int n = blockIdx.x * 4 + nl;               // 1250*4 = 5000 exactly

    float q[8];
    {
        const float* qp = g_q + (size_t)n * 256 + l * 8;
        float4 q0 = __ldg((const float4*)qp);
        float4 q1 = __ldg((const float4*)(qp + 4));
        q[0]=q0.x; q[1]=q0.y; q[2]=q0.z; q[3]=q0.w;
        q[4]=q1.x; q[5]=q1.y; q[6]=q1.z; q[7]=q1.w;
    }
    int s = __ldg(&g_rowptr[n]), e = __ldg(&g_rowptr[n + 1]);
    int mid = s + ((e - s) >> 1);
    int ws = half ? mid : s;
    int we = half ? e : mid;

    float den = 0.f;
    float acc[8] = {};
    int koff = l * 4;

    int nfull = (we - ws) >> 2;
    int i4 = ws;
    int nidx0, nidx1, nidx2, nidx3;
    if (nfull > 0) {
        nidx0 = __ldg(&g_csrsrc[i4]);     nidx1 = __ldg(&g_csrsrc[i4 + 1]);
        nidx2 = __ldg(&g_csrsrc[i4 + 2]); nidx3 = __ldg(&g_csrsrc[i4 + 3]);
    }
    for (int b = 0; b < nfull; b++) {
        int s0 = nidx0, s1 = nidx1, s2 = nidx2, s3 = nidx3;
        uint4 k0 = __ldg((const uint4*)(g_kh + (size_t)s0 * 128 + koff));
        uint4 k1 = __ldg((const uint4*)(g_kh + (size_t)s1 * 128 + koff));
        uint4 k2 = __ldg((const uint4*)(g_kh + (size_t)s2 * 128 + koff));
        uint4 k3 = __ldg((const uint4*)(g_kh + (size_t)s3 * 128 + koff));
        uint4 v0 = __ldg((const uint4*)(g_vh + (size_t)s0 * 128 + koff));
        uint4 v1 = __ldg((const uint4*)(g_vh + (size_t)s1 * 128 + koff));
        uint4 v2 = __ldg((const uint4*)(g_vh + (size_t)s2 * 128 + koff));
        uint4 v3 = __ldg((const uint4*)(g_vh + (size_t)s3 * 128 + koff));
        i4 += 4;
        if (b + 1 < nfull) {
            nidx0 = __ldg(&g_csrsrc[i4]);     nidx1 = __ldg(&g_csrsrc[i4 + 1]);
            nidx2 = __ldg(&g_csrsrc[i4 + 2]); nidx3 = __ldg(&g_csrsrc[i4 + 3]);
        }
        float d0 = dot8h(q, k0), d1 = dot8h(q, k1);
        float d2 = dot8h(q, k2), d3 = dot8h(q, k3);
#pragma unroll
        for (int r = 1; r <= 4; r <<= 1) {
            d0 += __shfl_xor_sync(0xffffffffu, d0, r);
            d1 += __shfl_xor_sync(0xffffffffu, d1, r);
            d2 += __shfl_xor_sync(0xffffffffu, d2, r);
            d3 += __shfl_xor_sync(0xffffffffu, d3, r);
        }
        float p0 = __expf(d0 * 0.125f), p1 = __expf(d1 * 0.125f);
        float p2 = __expf(d2 * 0.125f), p3 = __expf(d3 * 0.125f);
        den += (p0 + p1) + (p2 + p3);
        acc8h(acc, p0, v0); acc8h(acc, p1, v1);
        acc8h(acc, p2, v2); acc8h(acc, p3, v3);
    }
    for (int i = i4; i < we; i++) {
        int s0 = __ldg(&g_csrsrc[i]);
        uint4 k0 = __ldg((const uint4*)(g_kh + (size_t)s0 * 128 + koff));
        uint4 v0 = __ldg((const uint4*)(g_vh + (size_t)s0 * 128 + koff));
        float d0 = dot8h(q, k0);
#pragma unroll
        for (int r = 1; r <= 4; r <<= 1)
            d0 += __shfl_xor_sync(0xffffffffu, d0, r);
        float p0 = __expf(d0 * 0.125f);
        den += p0;
        acc8h(acc, p0, v0);
    }

    // combine halves: half-1 publishes, half-0 reduces + runs epilogue
    if (half) {
        *(float4*)&sPart[nl][l][0] = make_float4(acc[0], acc[1], acc[2], acc[3]);
        *(float4*)&sPart[nl][l][4] = make_float4(acc[4], acc[5], acc[6], acc[7]);
        sDen[nl][l] = den;
    }
    __syncthreads();
    if (half) return;

    den += sDen[nl][l];
    {
        float4 a0 = *(const float4*)&sPart[nl][l][0];
        float4 a1 = *(const float4*)&sPart[nl][l][4];
        acc[0] += a0.x; acc[1] += a0.y; acc[2] += a0.z; acc[3] += a0.w;
        acc[4] += a1.x; acc[5] += a1.y; acc[6] += a1.z; acc[7] += a1.w;
    }

    float inv = 0.25f * __fdividef(1.f, fmaxf(den, 1e-16f));
    float outv[8];
#pragma unroll
    for (int j = 0; j < 8; j++) {
        float ag = acc[j] * inv;
        ag += __shfl_xor_sync(0xffffffffu, ag, 8);
        ag += __shfl_xor_sync(0xffffffffu, ag, 16);
        outv[j] = ag;
    }
    int dbase = (l & 7) * 8;
    const float* skp = g_skip + (size_t)n * 64 + dbase;
    float4 s0f = __ldg((const float4*)skp);
    float4 s1f = __ldg((const float4*)(skp + 4));
    float sk[8] = {s0f.x, s0f.y, s0f.z, s0f.w, s1f.x, s1f.y, s1f.z, s1f.w};
    float tv[8];
#pragma unroll
    for (int j = 0; j < 8; j++) tv[j] = ftanh(outv[j] + sk[j]);

    float p8[8];
#pragma unroll
    for (int o = 0; o < 8; o++) {
        const float* wr = sWm + o * 64 + dbase;
        float4 w0 = *(const float4*)wr, w1 = *(const float4*)(wr + 4);
        p8[o] = tv[0]*w0.x + tv[1]*w0.y + tv[2]*w0.z + tv[3]*w0.w
              + tv[4]*w1.x + tv[5]*w1.y + tv[6]*w1.z + tv[7]*w1.w;
    }
#pragma unroll
    for (int o = 0; o < 8; o++) {
        p8[o] += __shfl_xor_sync(0xffffffffu, p8[o], 1);
        p8[o] += __shfl_xor_sync(0xffffffffu, p8[o], 2);
        p8[o] += __shfl_xor_sync(0xffffffffu, p8[o], 4);
    }
    if (l < 8) g_theta[((size_t)(t + 1) * NN + n) * 8 + l] = p8[l];
    if (l == 0) {
        union { unsigned u; __half2 h; } c0, c1, c2, c3;
        c0.h = __floats2half2_rn(p8[0], p8[1]);
        c1.h = __floats2half2_rn(p8[2], p8[3]);
        c2.h = __floats2half2_rn(p8[4], p8[5]);
        c3.h = __floats2half2_rn(p8[6], p8[7]);
        *(uint4*)(g_thetah + (size_t)n * 4) = make_uint4(c0.u, c1.u, c2.u, c3.u);
    }
}

// ---------------- final postprocess ----------------------------------------
__global__ void k_post(float* __restrict__ out) {
    int idx = blockIdx.x * 256 + threadIdx.x;
    if (idx >= NN * TT) return;
    int n = idx / TT, t = idx - n * TT;
    const float* th = g_theta + ((size_t)(t + 1) * NN + n) * 8;
    float4 a0 = *(const float4*)th, a1 = *(const float4*)(th + 4);
    float v5 = a1.y, v6 = a1.z, v7 = a1.w;
    float s5 = 1.f / (1.f + expf(-v5));
    float s6 = 1.f / (1.f + expf(-v6));
    float a = s5 * s6;
    float b = s5 - a;
    float cpl = fmaxf(v7, 0.f) + log1pf(expf(-fabsf(v7)));
    float* op = out + ((size_t)n * TT + t) * 8;
    *(float4*)op       = make_float4(a0.x, a0.y, a0.z, a0.w);
    *(float4*)(op + 4) = make_float4(a1.x, a, b, cpl);
}

// ---------------- launch ----------------------------------------------------
extern "C" void kernel_launch(void* const* d_in, const int* in_sizes, int n_in,
                              void* d_out, int out_size) {
    const float* x    = (const float*)d_in[0];
    const int*   ei   = (const int*)d_in[1];
    const float* Wih  = (const float*)d_in[2];
    const float* Whh  = (const float*)d_in[3];
    const float* bih  = (const float*)d_in[4];
    const float* bhh  = (const float*)d_in[5];
    const float* Wq   = (const float*)d_in[6];
    const float* bq   = (const float*)d_in[7];
    const float* Wk   = (const float*)d_in[8];
    const float* bk   = (const float*)d_in[9];
    const float* Wv   = (const float*)d_in[10];
    const float* bv   = (const float*)d_in[11];
    const float* Wsk  = (const float*)d_in[12];
    const float* bsk  = (const float*)d_in[13];
    const float* Wmlp = (const float*)d_in[14];

    k_initwprep<<<170, 256>>>(Wq, bq, Wk, bk, Wv, bv, Wsk, bsk);
    k_xw<<<dim3(79, 100), 256>>>(x, Wih, bih, bhh);
    k_lstm2<<<(NN + 31) / 32, 256>>>(Whh);
    k_gemm<<<dim3(7, 40), 256>>>(0);
    k_count<<<(EE + 255) / 256, 256>>>(ei);
    k_scan<<<1, 256>>>();
    k_scatter<<<(EE + 255) / 256, 256>>>(ei);
    k_edge<<<1250, 256>>>(0, Wmlp);

    for (int t = 1; t < TT; t++) {
        k_gemm<<<dim3(7, 40), 256>>>(t);
        k_edge<<<1250, 256>>>(t, Wmlp);
    }
    k_post<<<(NN * TT + 255) / 256, 256>>>((float*)d_out);
}